// round 5
// baseline (speedup 1.0000x reference)
#include <cuda_runtime.h>
#include <math_constants.h>

namespace {

constexpr int TOKENS   = 16384;
constexpr int NEXP     = 64;
constexpr int KDIM     = 2048;
constexpr int K_TOP    = 6;
constexpr int TILE_M   = 128;       // tokens per block
constexpr int KC       = 16;        // k-chunk
constexpr int NCH      = KDIM / KC; // 128 chunks
constexpr int NTHREADS = 128;
constexpr int XROW     = 132;       // xs row stride (TILE_M + 4)
constexpr int WROW     = 132;       // ws row stride (2*NEXP + 4), duplicated
constexpr int LROW     = 130;       // logitsT row stride (TILE_M + 2), even
constexpr float FP32_MIN_NORMAL = 1.17549435e-38f;  // 2^-126

struct __align__(16) Smem {
  union {
    struct {
      float xs[2][KC][XROW];   // [buf][k][token]      (k-major, natural)
      float ws[2][KC][WROW];   // [buf][k][2*expert]   (duplicated {w,w})
    } mm;
    float logitsT[NEXP][LROW]; // [expert][token]
  };
};

__device__ __forceinline__ void fma2(unsigned long long& d,
                                     unsigned long long a,
                                     unsigned long long b) {
  // packed fp32x2 fused MAC: 2 IEEE FMAs per instruction, per-lane chains
  // identical to scalar sequential-k FFMA.
  asm("fma.rn.f32x2 %0, %1, %2, %0;" : "+l"(d) : "l"(a), "l"(b));
}

__device__ __forceinline__ unsigned long long pack2(float a, float b) {
  float2 t = make_float2(a, b);
  return *reinterpret_cast<unsigned long long*>(&t);
}

}  // namespace

__global__ void __launch_bounds__(NTHREADS, 1)
gate_kernel(const float* __restrict__ x, const float* __restrict__ w,
            float* __restrict__ outw, float* __restrict__ outi)
{
  __shared__ Smem sm;

  const int tid = threadIdx.x;
  const int eg  = tid >> 4;    // expert group: experts eg*8 .. +7  (2 per warp)
  const int tg  = tid & 15;    // token group : tokens tg*4..+3 and 64+tg*4..+3
  const int tile0 = blockIdx.x * TILE_M;

  const float4* __restrict__ x4 = reinterpret_cast<const float4*>(x);
  const float4* __restrict__ w4 = reinterpret_cast<const float4*>(w);
  const int rowF4 = KDIM / 4;  // 512 float4 per row

  // ---- global-load indexing ------------------------------------------------
  // x: TILE_M*KC = 2048 floats = 512 float4 per chunk -> 4 per thread
  // w: NEXP*KC   = 1024 floats = 256 float4 per chunk -> 2 per thread
  int xtok[4], xk4[4];
  long xix[4];
#pragma unroll
  for (int i = 0; i < 4; ++i) {
    const int f = tid + i * NTHREADS;
    xtok[i] = f >> 2;
    xk4[i]  = f & 3;
    xix[i]  = (long)(tile0 + xtok[i]) * rowF4 + xk4[i];
  }
  int wexp[2], wk4[2];
  long wix[2];
#pragma unroll
  for (int i = 0; i < 2; ++i) {
    const int f = tid + i * NTHREADS;
    wexp[i] = f >> 2;
    wk4[i]  = f & 3;
    wix[i]  = (long)wexp[i] * rowF4 + wk4[i];
  }

  float4 xst[4], wst[2];

  // ---- prologue: chunk 0 -> buf 0 -----------------------------------------
#pragma unroll
  for (int i = 0; i < 4; ++i) xst[i] = x4[xix[i]];
#pragma unroll
  for (int i = 0; i < 2; ++i) wst[i] = w4[wix[i]];

#pragma unroll
  for (int i = 0; i < 4; ++i) {
    sm.mm.xs[0][xk4[i] * 4 + 0][xtok[i]] = xst[i].x;
    sm.mm.xs[0][xk4[i] * 4 + 1][xtok[i]] = xst[i].y;
    sm.mm.xs[0][xk4[i] * 4 + 2][xtok[i]] = xst[i].z;
    sm.mm.xs[0][xk4[i] * 4 + 3][xtok[i]] = xst[i].w;
  }
#pragma unroll
  for (int i = 0; i < 2; ++i) {
    float2* wsrow0 = reinterpret_cast<float2*>(
        &sm.mm.ws[0][wk4[i] * 4 + 0][2 * wexp[i]]);
    float2* wsrow1 = reinterpret_cast<float2*>(
        &sm.mm.ws[0][wk4[i] * 4 + 1][2 * wexp[i]]);
    float2* wsrow2 = reinterpret_cast<float2*>(
        &sm.mm.ws[0][wk4[i] * 4 + 2][2 * wexp[i]]);
    float2* wsrow3 = reinterpret_cast<float2*>(
        &sm.mm.ws[0][wk4[i] * 4 + 3][2 * wexp[i]]);
    *wsrow0 = make_float2(wst[i].x, wst[i].x);
    *wsrow1 = make_float2(wst[i].y, wst[i].y);
    *wsrow2 = make_float2(wst[i].z, wst[i].z);
    *wsrow3 = make_float2(wst[i].w, wst[i].w);
  }
  __syncthreads();

  // ---- accumulators: 8 experts x 4 token-pairs, each f32x2 -----------------
  unsigned long long acc[8][4];
#pragma unroll
  for (int e = 0; e < 8; ++e)
#pragma unroll
    for (int p = 0; p < 4; ++p) acc[e][p] = 0ULL;

  // ---- mainloop ------------------------------------------------------------
  for (int c = 0; c < NCH; ++c) {
    const int buf = c & 1;

    if (c + 1 < NCH) {
      const long off = (long)(c + 1) * (KC / 4);
#pragma unroll
      for (int i = 0; i < 4; ++i) xst[i] = x4[xix[i] + off];
#pragma unroll
      for (int i = 0; i < 2; ++i) wst[i] = w4[wix[i] + off];
    }

#pragma unroll
    for (int kk = 0; kk < KC; ++kk) {
      // x: 8 tokens as two LDS.128 (16 distinct lines/warp, conflict-free
      // within quarter-warps thanks to the tg*4 / 64+tg*4 split)
      const float4 xq0 = *reinterpret_cast<const float4*>(
          &sm.mm.xs[buf][kk][tg * 4]);
      const float4 xq1 = *reinterpret_cast<const float4*>(
          &sm.mm.xs[buf][kk][64 + tg * 4]);
      unsigned long long xp[4];
      xp[0] = pack2(xq0.x, xq0.y);
      xp[1] = pack2(xq0.z, xq0.w);
      xp[2] = pack2(xq1.x, xq1.y);
      xp[3] = pack2(xq1.z, xq1.w);

      // w: 8 duplicated experts as four LDS.128 — only 2 distinct lines per
      // warp (2 expert-groups) => broadcast, ~1 cycle each
      const float4 wv0 = *reinterpret_cast<const float4*>(
          &sm.mm.ws[buf][kk][eg * 16 + 0]);
      const float4 wv1 = *reinterpret_cast<const float4*>(
          &sm.mm.ws[buf][kk][eg * 16 + 4]);
      const float4 wv2 = *reinterpret_cast<const float4*>(
          &sm.mm.ws[buf][kk][eg * 16 + 8]);
      const float4 wv3 = *reinterpret_cast<const float4*>(
          &sm.mm.ws[buf][kk][eg * 16 + 12]);
      unsigned long long wd[8];
      wd[0] = pack2(wv0.x, wv0.y);  // expert eg*8+0 duplicated
      wd[1] = pack2(wv0.z, wv0.w);  // expert eg*8+1
      wd[2] = pack2(wv1.x, wv1.y);
      wd[3] = pack2(wv1.z, wv1.w);
      wd[4] = pack2(wv2.x, wv2.y);
      wd[5] = pack2(wv2.z, wv2.w);
      wd[6] = pack2(wv3.x, wv3.y);
      wd[7] = pack2(wv3.z, wv3.w);

#pragma unroll
      for (int e = 0; e < 8; ++e)
#pragma unroll
        for (int p = 0; p < 4; ++p)
          fma2(acc[e][p], wd[e], xp[p]);
    }

    if (c + 1 < NCH) {
      const int nb = buf ^ 1;
#pragma unroll
      for (int i = 0; i < 4; ++i) {
        sm.mm.xs[nb][xk4[i] * 4 + 0][xtok[i]] = xst[i].x;
        sm.mm.xs[nb][xk4[i] * 4 + 1][xtok[i]] = xst[i].y;
        sm.mm.xs[nb][xk4[i] * 4 + 2][xtok[i]] = xst[i].z;
        sm.mm.xs[nb][xk4[i] * 4 + 3][xtok[i]] = xst[i].w;
      }
#pragma unroll
      for (int i = 0; i < 2; ++i) {
        float2* r0 = reinterpret_cast<float2*>(
            &sm.mm.ws[nb][wk4[i] * 4 + 0][2 * wexp[i]]);
        float2* r1 = reinterpret_cast<float2*>(
            &sm.mm.ws[nb][wk4[i] * 4 + 1][2 * wexp[i]]);
        float2* r2 = reinterpret_cast<float2*>(
            &sm.mm.ws[nb][wk4[i] * 4 + 2][2 * wexp[i]]);
        float2* r3 = reinterpret_cast<float2*>(
            &sm.mm.ws[nb][wk4[i] * 4 + 3][2 * wexp[i]]);
        *r0 = make_float2(wst[i].x, wst[i].x);
        *r1 = make_float2(wst[i].y, wst[i].y);
        *r2 = make_float2(wst[i].z, wst[i].z);
        *r3 = make_float2(wst[i].w, wst[i].w);
      }
    }
    __syncthreads();
  }

  // ---- epilogue: logits -> smem (transposed [expert][token]) ---------------
#pragma unroll
  for (int e = 0; e < 8; ++e)
#pragma unroll
    for (int p = 0; p < 4; ++p) {
      const float2 v = *reinterpret_cast<float2*>(&acc[e][p]);
      const int tokbase = ((p & 2) ? 64 : 0) + tg * 4 + (p & 1) * 2;
      *reinterpret_cast<float2*>(&sm.logitsT[eg * 8 + e][tokbase]) = v;
    }
  __syncthreads();

  // ---- per-token softmax (FTZ like XLA:GPU) + stable top-6 -----------------
  {
    const int tok = tid;

    float mx = -CUDART_INF_F;
#pragma unroll 8
    for (int e = 0; e < NEXP; ++e) mx = fmaxf(mx, sm.logitsT[e][tok]);

    float sum = 0.0f;
#pragma unroll 8
    for (int e = 0; e < NEXP; ++e) sum += expf(sm.logitsT[e][tok] - mx);

    float bv[K_TOP];
    int   bi[K_TOP];
#pragma unroll
    for (int j = 0; j < K_TOP; ++j) { bv[j] = -CUDART_INF_F; bi[j] = 0; }

    for (int e = 0; e < NEXP; ++e) {
      float s = expf(sm.logitsT[e][tok] - mx) / sum;
      // XLA:GPU softmax is FTZ: subnormal scores become exactly 0.0 and
      // top_k tie-breaks among the zeros by lowest index. Replicate.
      if (s < FP32_MIN_NORMAL) s = 0.0f;
      if (s > bv[K_TOP - 1]) {
        bv[K_TOP - 1] = s;
        bi[K_TOP - 1] = e;
#pragma unroll
        for (int j = K_TOP - 1; j > 0; --j) {
          if (bv[j] > bv[j - 1]) {
            const float tv = bv[j]; bv[j] = bv[j - 1]; bv[j - 1] = tv;
            const int   ti = bi[j]; bi[j] = bi[j - 1]; bi[j - 1] = ti;
          }
        }
      }
    }

    const long gt = tile0 + tok;
#pragma unroll
    for (int j = 0; j < K_TOP; ++j) {
      outw[gt * K_TOP + j] = bv[j];
      outi[gt * K_TOP + j] = (float)bi[j];
    }
  }
}

extern "C" void kernel_launch(void* const* d_in, const int* in_sizes, int n_in,
                              void* d_out, int out_size) {
  const float* a = (const float*)d_in[0];
  const float* b = (const float*)d_in[1];
  const float* x = a;
  const float* w = b;
  if (n_in >= 2 && in_sizes[0] == NEXP * KDIM && in_sizes[1] == TOKENS * KDIM) {
    x = b; w = a;
  }

  float* out  = (float*)d_out;
  float* outw = out;                         // weights [16384, 6]
  float* outi = out + (long)TOKENS * K_TOP;  // indices (as float) [16384, 6]

  gate_kernel<<<TOKENS / TILE_M, NTHREADS>>>(x, w, outw, outi);
}